// round 3
// baseline (speedup 1.0000x reference)
#include <cuda_runtime.h>

#define T_LEN 4995
#define BATCH 64
#define VOCAB 4096
#define EDIM  100
#define UDIM  64
#define G3    192   // 3*U gate width
#define NTHR  384

// Precomputed (emb @ W1 + b1[0]) table: [VOCAB, 192]
__device__ float g_tab[VOCAB * G3];

__device__ __forceinline__ void ffma2(float2& acc, const float2 a, const float2 b) {
    asm("fma.rn.f32x2 %0, %1, %2, %0;"
        : "+l"(reinterpret_cast<unsigned long long&>(acc))
        : "l"(*reinterpret_cast<const unsigned long long*>(&a)),
          "l"(*reinterpret_cast<const unsigned long long*>(&b)));
}

__device__ __forceinline__ float sigf(float x) {
    return 1.0f / (1.0f + __expf(-x));
}
__device__ __forceinline__ float tanh_fast(float x) {
    float e = __expf(2.0f * x);
    return (e - 1.0f) * __fdividef(1.0f, e + 1.0f);
}

// ---------------------------------------------------------------------------
// Kernel 1: g_tab[v][j] = sum_e emb[v][e] * W1[e][j] + b1[0][j]
// ---------------------------------------------------------------------------
__global__ void build_tab(const float* __restrict__ emb,
                          const float* __restrict__ W1,
                          const float* __restrict__ b1) {
    __shared__ float es[EDIM];
    const int v = blockIdx.x;
    const int j = threadIdx.x;
    for (int e = j; e < EDIM; e += G3) es[e] = emb[v * EDIM + e];
    __syncthreads();
    float s = b1[j];
#pragma unroll 4
    for (int e = 0; e < EDIM; e++) s += es[e] * __ldg(&W1[e * G3 + j]);
    g_tab[v * G3 + j] = s;
}

// ---------------------------------------------------------------------------
// Kernel 2: fused 2-layer GRU, skewed pipeline, one CTA per batch row.
//
// Slot s (single __syncthreads per slot, all roles concurrent):
//   role A (warps 0-3,  tid   0..127): h1[s]   = GRU1(h1[s-1], xt[s])
//   role C (warps 4-7,  tid 128..255): x2[s-1] = h1[s-1] @ W2 + b2[0]
//   role B (warps 8-11, tid 256..383): h2[s-2] = GRU2gate(h2[s-3], x2[s-2])
// Each column handled by a lane PAIR (half-dots of 32, shfl.xor combine).
// Warp w -> SMSP w&3, so every SMSP runs exactly one warp of each role.
// ---------------------------------------------------------------------------
__global__ void __launch_bounds__(NTHR, 1)
gru_fused(const int*   __restrict__ tokens,
          const float* __restrict__ U1w,
          const float* __restrict__ b1,
          const float* __restrict__ W2w,
          const float* __restrict__ U2w,
          const float* __restrict__ b2,
          const float* __restrict__ Wout,
          const float* __restrict__ bout,
          float*       __restrict__ out) {
    __shared__ int   toks[T_LEN];
    __shared__ __align__(16) float h1s[2][UDIM];   // double-buffered h1
    __shared__ __align__(16) float h2s[2][UDIM];   // double-buffered h2
    __shared__ __align__(16) float x2s[2][G3];     // double-buffered x2 = h1@W2+b2[0]
    __shared__ __align__(16) float xtr[4][G3];     // xt ring, prefetch distance 3
    __shared__ __align__(16) float red[UDIM];

    const int tid = threadIdx.x;
    const int b   = blockIdx.x;

    if (tid < UDIM) {
        h1s[0][tid] = 0.0f; h1s[1][tid] = 0.0f;
        h2s[0][tid] = 0.0f; h2s[1][tid] = 0.0f;
    }
    for (int i = tid; i < T_LEN; i += NTHR)
        toks[i] = tokens[(long long)b * T_LEN + i];
    __syncthreads();
    for (int i = tid; i < 3 * G3; i += NTHR) {
        const int tp = i / G3, jj = i % G3;
        xtr[tp][jj] = g_tab[toks[tp] * G3 + jj];
    }
    __syncthreads();

    const int role = tid >> 7;       // 0: A(layer1), 1: C(x2), 2: B(layer2)
    const int t2   = tid & 127;
    const int col  = t2 >> 1;
    const int half = t2 & 1;

    // ---- per-thread register weights: half-dot (32 k-values) x 3 gates ----
    const float* Wm = (role == 0) ? U1w : (role == 1) ? W2w : U2w;
    float2 w[3][16];
#pragma unroll
    for (int g = 0; g < 3; g++)
#pragma unroll
        for (int m = 0; m < 16; m++) {
            const int k = half * 32 + 2 * m;
            w[g][m] = make_float2(Wm[k * G3 + g * 64 + col],
                                  Wm[(k + 1) * G3 + g * 64 + col]);
        }
    float bias[3];
#pragma unroll
    for (int g = 0; g < 3; g++) {
        float bv;
        if (role == 0)      bv = b1[G3 + g * 64 + col];   // recurrent bias L1
        else if (role == 1) bv = b2[g * 64 + col];        // input bias L2
        else                bv = b2[G3 + g * 64 + col];   // recurrent bias L2
        bias[g] = (half == 0) ? bv : 0.0f;
    }

    for (int s = 0; s < T_LEN + 2; s++) {
        if (role == 0) {
            // -------- prefetch xt for slot s+3 --------
            const int tp = s + 3;
            if (tp < T_LEN) {
                const int tok = toks[tp];
                xtr[tp & 3][t2] = g_tab[tok * G3 + t2];
                if (t2 < 64) xtr[tp & 3][128 + t2] = g_tab[tok * G3 + 128 + t2];
            }
            if (s < T_LEN) {
                // h1[s] from h1[s-1] (buffer (s+1)&1) and xt[s]
                const float2* hv = (const float2*)(h1s[(s + 1) & 1]) + half * 16;
                float2 a0 = {bias[0], 0.f}, a1 = {0.f, 0.f};
                float2 r0 = {bias[1], 0.f}, r1 = {0.f, 0.f};
                float2 c0 = {bias[2], 0.f}, c1 = {0.f, 0.f};
#pragma unroll
                for (int m = 0; m < 16; m += 2) {
                    const float2 h0 = hv[m], h1v = hv[m + 1];
                    ffma2(a0, h0, w[0][m]); ffma2(a1, h1v, w[0][m + 1]);
                    ffma2(r0, h0, w[1][m]); ffma2(r1, h1v, w[1][m + 1]);
                    ffma2(c0, h0, w[2][m]); ffma2(c1, h1v, w[2][m + 1]);
                }
                float az = a0.x + a0.y + a1.x + a1.y;
                float ar = r0.x + r0.y + r1.x + r1.y;
                float ah = c0.x + c0.y + c1.x + c1.y;
                az += __shfl_xor_sync(0xFFFFFFFFu, az, 1);
                ar += __shfl_xor_sync(0xFFFFFFFFu, ar, 1);
                ah += __shfl_xor_sync(0xFFFFFFFFu, ah, 1);
                const float xz = xtr[s & 3][col];
                const float xr = xtr[s & 3][64 + col];
                const float xh = xtr[s & 3][128 + col];
                const float z  = sigf(xz + az);
                const float r  = sigf(xr + ar);
                const float hh = tanh_fast(xh + r * ah);
                const float hold = h1s[(s + 1) & 1][col];
                if (half == 0)
                    h1s[s & 1][col] = z * hold + (1.0f - z) * hh;
            }
        } else if (role == 1) {
            if (s >= 1 && s <= T_LEN) {
                // x2[s-1] = h1[s-1] @ W2 + b2[0]; h1[s-1] in buffer (s-1)&1
                const float2* hv = (const float2*)(h1s[(s + 1) & 1]) + half * 16;
                float2 a0 = {bias[0], 0.f}, a1 = {0.f, 0.f};
                float2 r0 = {bias[1], 0.f}, r1 = {0.f, 0.f};
                float2 c0 = {bias[2], 0.f}, c1 = {0.f, 0.f};
#pragma unroll
                for (int m = 0; m < 16; m += 2) {
                    const float2 h0 = hv[m], h1v = hv[m + 1];
                    ffma2(a0, h0, w[0][m]); ffma2(a1, h1v, w[0][m + 1]);
                    ffma2(r0, h0, w[1][m]); ffma2(r1, h1v, w[1][m + 1]);
                    ffma2(c0, h0, w[2][m]); ffma2(c1, h1v, w[2][m + 1]);
                }
                float sz = a0.x + a0.y + a1.x + a1.y;
                float sr = r0.x + r0.y + r1.x + r1.y;
                float sh = c0.x + c0.y + c1.x + c1.y;
                sz += __shfl_xor_sync(0xFFFFFFFFu, sz, 1);
                sr += __shfl_xor_sync(0xFFFFFFFFu, sr, 1);
                sh += __shfl_xor_sync(0xFFFFFFFFu, sh, 1);
                if (half == 0) {
                    float* dst = x2s[(s + 1) & 1];   // buffer (s-1)&1
                    dst[col]       = sz;
                    dst[64 + col]  = sr;
                    dst[128 + col] = sh;
                }
            }
        } else {
            if (s >= 2 && s <= T_LEN + 1) {
                // h2[s-2] from h2[s-3] (buffer (s-1)&1) and x2[s-2] (buffer s&1)
                const float2* hv = (const float2*)(h2s[(s + 1) & 1]) + half * 16;
                float2 a0 = {bias[0], 0.f}, a1 = {0.f, 0.f};
                float2 r0 = {bias[1], 0.f}, r1 = {0.f, 0.f};
                float2 c0 = {bias[2], 0.f}, c1 = {0.f, 0.f};
#pragma unroll
                for (int m = 0; m < 16; m += 2) {
                    const float2 h0 = hv[m], h1v = hv[m + 1];
                    ffma2(a0, h0, w[0][m]); ffma2(a1, h1v, w[0][m + 1]);
                    ffma2(r0, h0, w[1][m]); ffma2(r1, h1v, w[1][m + 1]);
                    ffma2(c0, h0, w[2][m]); ffma2(c1, h1v, w[2][m + 1]);
                }
                float az = a0.x + a0.y + a1.x + a1.y;
                float ar = r0.x + r0.y + r1.x + r1.y;
                float ah = c0.x + c0.y + c1.x + c1.y;
                az += __shfl_xor_sync(0xFFFFFFFFu, az, 1);
                ar += __shfl_xor_sync(0xFFFFFFFFu, ar, 1);
                ah += __shfl_xor_sync(0xFFFFFFFFu, ah, 1);
                const float xz = x2s[s & 1][col];
                const float xr = x2s[s & 1][64 + col];
                const float xh = x2s[s & 1][128 + col];
                const float z  = sigf(xz + az);
                const float r  = sigf(xr + ar);
                const float hh = tanh_fast(xh + r * ah);
                const float hold = h2s[(s + 1) & 1][col];
                if (half == 0)
                    h2s[s & 1][col] = z * hold + (1.0f - z) * hh;
            }
        }
        __syncthreads();
    }

    // ---------------- Epilogue: sigmoid(h2[T-1] @ Wout + bout) ----------------
    if (tid < UDIM) red[tid] = h2s[(T_LEN + 1) & 1][tid] * Wout[tid];
    __syncthreads();
    if (tid == 0) {
        float s = bout[0];
#pragma unroll
        for (int k = 0; k < UDIM; k++) s += red[k];
        out[b] = 1.0f / (1.0f + __expf(-s));
    }
}

// ---------------------------------------------------------------------------
extern "C" void kernel_launch(void* const* d_in, const int* in_sizes, int n_in,
                              void* d_out, int out_size) {
    const int*   tokens = (const int*)  d_in[0];
    const float* emb    = (const float*)d_in[1];
    const float* W1     = (const float*)d_in[2];
    const float* U1     = (const float*)d_in[3];
    const float* b1     = (const float*)d_in[4];
    const float* W2     = (const float*)d_in[5];
    const float* U2     = (const float*)d_in[6];
    const float* b2     = (const float*)d_in[7];
    const float* Wout   = (const float*)d_in[8];
    const float* bout   = (const float*)d_in[9];

    build_tab<<<VOCAB, G3>>>(emb, W1, b1);
    gru_fused<<<BATCH, NTHR>>>(tokens, U1, b1, W2, U2, b2, Wout, bout,
                               (float*)d_out);
}

// round 4
// speedup vs baseline: 1.2273x; 1.2273x over previous
#include <cuda_runtime.h>

#define T_LEN 4995
#define BATCH 64
#define VOCAB 4096
#define EDIM  100
#define UDIM  64
#define G3    192   // 3*U gate width
#define NTHR  384

// Precomputed (emb @ W1 + b1[0]) table: [VOCAB, 192]
__device__ __align__(16) float g_tab[VOCAB * G3];

__device__ __forceinline__ void ffma2(float2& acc, const float2 a, const float2 b) {
    asm("fma.rn.f32x2 %0, %1, %2, %0;"
        : "+l"(reinterpret_cast<unsigned long long&>(acc))
        : "l"(*reinterpret_cast<const unsigned long long*>(&a)),
          "l"(*reinterpret_cast<const unsigned long long*>(&b)));
}

__device__ __forceinline__ float sigf(float x) {
    return 1.0f / (1.0f + __expf(-x));
}
__device__ __forceinline__ float tanh_fast(float x) {
    float e = __expf(2.0f * x);
    return (e - 1.0f) * __fdividef(1.0f, e + 1.0f);
}

// ---------------------------------------------------------------------------
// Kernel 1: g_tab[v][j] = sum_e emb[v][e] * W1[e][j] + b1[0][j]
// ---------------------------------------------------------------------------
__global__ void build_tab(const float* __restrict__ emb,
                          const float* __restrict__ W1,
                          const float* __restrict__ b1) {
    __shared__ float es[EDIM];
    const int v = blockIdx.x;
    const int j = threadIdx.x;
    for (int e = j; e < EDIM; e += G3) es[e] = emb[v * EDIM + e];
    __syncthreads();
    float s = b1[j];
#pragma unroll 4
    for (int e = 0; e < EDIM; e++) s += es[e] * __ldg(&W1[e * G3 + j]);
    g_tab[v * G3 + j] = s;
}

// ---------------------------------------------------------------------------
// Kernel 2: fused 2-layer GRU, skewed pipeline, one CTA per batch row.
//
// Slot s (single __syncthreads per slot, all roles concurrent):
//   role A (warps 0-3,  tid   0..127): h1[s]   = GRU1(h1[s-1], xt[s])
//                                      + cp.async prefetch of xt[s+3]
//   role C (warps 4-7,  tid 128..255): x2[s-1] = h1[s-1] @ W2 + b2[0]
//   role B (warps 8-11, tid 256..383): h2[s-2] = GRU2gate(h2[s-3], x2[s-2])
// Each column handled by a lane PAIR (half-dots of 32, shfl.xor combine).
// xt prefetch uses cp.async (LDGSTS): no LDG->STS register round-trip on the
// critical path, and bar.sync does NOT drain outstanding cp.async groups.
// ---------------------------------------------------------------------------
__global__ void __launch_bounds__(NTHR, 1)
gru_fused(const int*   __restrict__ tokens,
          const float* __restrict__ U1w,
          const float* __restrict__ b1,
          const float* __restrict__ W2w,
          const float* __restrict__ U2w,
          const float* __restrict__ b2,
          const float* __restrict__ Wout,
          const float* __restrict__ bout,
          float*       __restrict__ out) {
    __shared__ int   toks[T_LEN];
    __shared__ __align__(16) float h1s[2][UDIM];   // double-buffered h1
    __shared__ __align__(16) float h2s[2][UDIM];   // double-buffered h2
    __shared__ __align__(16) float x2s[2][G3];     // double-buffered x2 = h1@W2+b2[0]
    __shared__ __align__(16) float xtr[4][G3];     // xt ring, prefetch distance 3
    __shared__ __align__(16) float red[UDIM];

    const int tid = threadIdx.x;
    const int b   = blockIdx.x;

    if (tid < UDIM) {
        h1s[0][tid] = 0.0f; h1s[1][tid] = 0.0f;
        h2s[0][tid] = 0.0f; h2s[1][tid] = 0.0f;
    }
    for (int i = tid; i < T_LEN; i += NTHR)
        toks[i] = tokens[(long long)b * T_LEN + i];
    __syncthreads();
    for (int i = tid; i < 3 * G3; i += NTHR) {
        const int tp = i / G3, jj = i % G3;
        xtr[tp][jj] = g_tab[toks[tp] * G3 + jj];
    }
    __syncthreads();

    const int role = tid >> 7;       // 0: A(layer1), 1: C(x2), 2: B(layer2)
    const int t2   = tid & 127;
    const int col  = t2 >> 1;
    const int half = t2 & 1;

    // ---- per-thread register weights: half-dot (32 k-values) x 3 gates ----
    const float* Wm = (role == 0) ? U1w : (role == 1) ? W2w : U2w;
    float2 w[3][16];
#pragma unroll
    for (int g = 0; g < 3; g++)
#pragma unroll
        for (int m = 0; m < 16; m++) {
            const int k = half * 32 + 2 * m;
            w[g][m] = make_float2(Wm[k * G3 + g * 64 + col],
                                  Wm[(k + 1) * G3 + g * 64 + col]);
        }
    float bias[3];
#pragma unroll
    for (int g = 0; g < 3; g++) {
        float bv;
        if (role == 0)      bv = b1[G3 + g * 64 + col];   // recurrent bias L1
        else if (role == 1) bv = b2[g * 64 + col];        // input bias L2
        else                bv = b2[G3 + g * 64 + col];   // recurrent bias L2
        bias[g] = (half == 0) ? bv : 0.0f;
    }

    for (int s = 0; s < T_LEN + 2; s++) {
        if (role == 0) {
            // -------- async prefetch of xt for slot s+3 (16B x 48 lanes) ----
            if (t2 < 48) {
                const int tp = s + 3;
                if (tp < T_LEN) {
                    const int tok = toks[tp];
                    const float* src = g_tab + tok * G3 + t2 * 4;
                    unsigned dst = (unsigned)__cvta_generic_to_shared(
                        &xtr[tp & 3][t2 * 4]);
                    asm volatile("cp.async.cg.shared.global [%0], [%1], 16;"
                                 :: "r"(dst), "l"(src) : "memory");
                }
                asm volatile("cp.async.commit_group;" ::: "memory");
            }
            if (s < T_LEN) {
                // h1[s] from h1[s-1] (buffer (s+1)&1) and xt[s]
                const float2* hv = (const float2*)(h1s[(s + 1) & 1]) + half * 16;
                float2 a0 = {bias[0], 0.f}, a1 = {0.f, 0.f};
                float2 r0 = {bias[1], 0.f}, r1 = {0.f, 0.f};
                float2 c0 = {bias[2], 0.f}, c1 = {0.f, 0.f};
#pragma unroll
                for (int m = 0; m < 16; m += 2) {
                    const float2 h0 = hv[m], h1v = hv[m + 1];
                    ffma2(a0, h0, w[0][m]); ffma2(a1, h1v, w[0][m + 1]);
                    ffma2(r0, h0, w[1][m]); ffma2(r1, h1v, w[1][m + 1]);
                    ffma2(c0, h0, w[2][m]); ffma2(c1, h1v, w[2][m + 1]);
                }
                float az = a0.x + a0.y + a1.x + a1.y;
                float ar = r0.x + r0.y + r1.x + r1.y;
                float ah = c0.x + c0.y + c1.x + c1.y;
                az += __shfl_xor_sync(0xFFFFFFFFu, az, 1);
                ar += __shfl_xor_sync(0xFFFFFFFFu, ar, 1);
                ah += __shfl_xor_sync(0xFFFFFFFFu, ah, 1);
                const float xz = xtr[s & 3][col];
                const float xr = xtr[s & 3][64 + col];
                const float xh = xtr[s & 3][128 + col];
                const float z  = sigf(xz + az);
                const float r  = sigf(xr + ar);
                const float hh = tanh_fast(xh + r * ah);
                const float hold = h1s[(s + 1) & 1][col];
                if (half == 0)
                    h1s[s & 1][col] = z * hold + (1.0f - z) * hh;
            }
            // Complete the group issued at slot s-2 (data for slot s+1)
            // BEFORE the barrier so it is visible to all threads after it.
            if (t2 < 48)
                asm volatile("cp.async.wait_group 2;" ::: "memory");
        } else if (role == 1) {
            if (s >= 1 && s <= T_LEN) {
                // x2[s-1] = h1[s-1] @ W2 + b2[0]; h1[s-1] in buffer (s-1)&1
                const float2* hv = (const float2*)(h1s[(s + 1) & 1]) + half * 16;
                float2 a0 = {bias[0], 0.f}, a1 = {0.f, 0.f};
                float2 r0 = {bias[1], 0.f}, r1 = {0.f, 0.f};
                float2 c0 = {bias[2], 0.f}, c1 = {0.f, 0.f};
#pragma unroll
                for (int m = 0; m < 16; m += 2) {
                    const float2 h0 = hv[m], h1v = hv[m + 1];
                    ffma2(a0, h0, w[0][m]); ffma2(a1, h1v, w[0][m + 1]);
                    ffma2(r0, h0, w[1][m]); ffma2(r1, h1v, w[1][m + 1]);
                    ffma2(c0, h0, w[2][m]); ffma2(c1, h1v, w[2][m + 1]);
                }
                float sz = a0.x + a0.y + a1.x + a1.y;
                float sr = r0.x + r0.y + r1.x + r1.y;
                float sh = c0.x + c0.y + c1.x + c1.y;
                sz += __shfl_xor_sync(0xFFFFFFFFu, sz, 1);
                sr += __shfl_xor_sync(0xFFFFFFFFu, sr, 1);
                sh += __shfl_xor_sync(0xFFFFFFFFu, sh, 1);
                if (half == 0) {
                    float* dst = x2s[(s + 1) & 1];   // buffer (s-1)&1
                    dst[col]       = sz;
                    dst[64 + col]  = sr;
                    dst[128 + col] = sh;
                }
            }
        } else {
            if (s >= 2 && s <= T_LEN + 1) {
                // h2[s-2] from h2[s-3] (buffer (s-1)&1) and x2[s-2] (buffer s&1)
                const float2* hv = (const float2*)(h2s[(s + 1) & 1]) + half * 16;
                float2 a0 = {bias[0], 0.f}, a1 = {0.f, 0.f};
                float2 r0 = {bias[1], 0.f}, r1 = {0.f, 0.f};
                float2 c0 = {bias[2], 0.f}, c1 = {0.f, 0.f};
#pragma unroll
                for (int m = 0; m < 16; m += 2) {
                    const float2 h0 = hv[m], h1v = hv[m + 1];
                    ffma2(a0, h0, w[0][m]); ffma2(a1, h1v, w[0][m + 1]);
                    ffma2(r0, h0, w[1][m]); ffma2(r1, h1v, w[1][m + 1]);
                    ffma2(c0, h0, w[2][m]); ffma2(c1, h1v, w[2][m + 1]);
                }
                float az = a0.x + a0.y + a1.x + a1.y;
                float ar = r0.x + r0.y + r1.x + r1.y;
                float ah = c0.x + c0.y + c1.x + c1.y;
                az += __shfl_xor_sync(0xFFFFFFFFu, az, 1);
                ar += __shfl_xor_sync(0xFFFFFFFFu, ar, 1);
                ah += __shfl_xor_sync(0xFFFFFFFFu, ah, 1);
                const float xz = x2s[s & 1][col];
                const float xr = x2s[s & 1][64 + col];
                const float xh = x2s[s & 1][128 + col];
                const float z  = sigf(xz + az);
                const float r  = sigf(xr + ar);
                const float hh = tanh_fast(xh + r * ah);
                const float hold = h2s[(s + 1) & 1][col];
                if (half == 0)
                    h2s[s & 1][col] = z * hold + (1.0f - z) * hh;
            }
        }
        __syncthreads();
    }

    // ---------------- Epilogue: sigmoid(h2[T-1] @ Wout + bout) ----------------
    if (tid < UDIM) red[tid] = h2s[(T_LEN + 1) & 1][tid] * Wout[tid];
    __syncthreads();
    if (tid == 0) {
        float s = bout[0];
#pragma unroll
        for (int k = 0; k < UDIM; k++) s += red[k];
        out[b] = 1.0f / (1.0f + __expf(-s));
    }
}

// ---------------------------------------------------------------------------
extern "C" void kernel_launch(void* const* d_in, const int* in_sizes, int n_in,
                              void* d_out, int out_size) {
    const int*   tokens = (const int*)  d_in[0];
    const float* emb    = (const float*)d_in[1];
    const float* W1     = (const float*)d_in[2];
    const float* U1     = (const float*)d_in[3];
    const float* b1     = (const float*)d_in[4];
    const float* W2     = (const float*)d_in[5];
    const float* U2     = (const float*)d_in[6];
    const float* b2     = (const float*)d_in[7];
    const float* Wout   = (const float*)d_in[8];
    const float* bout   = (const float*)d_in[9];

    build_tab<<<VOCAB, G3>>>(emb, W1, b1);
    gru_fused<<<BATCH, NTHR>>>(tokens, U1, b1, W2, U2, b2, Wout, bout,
                               (float*)d_out);
}